// round 2
// baseline (speedup 1.0000x reference)
#include <cuda_runtime.h>
#include <cstdint>

#define LEN      2048
#define BM       128      // query rows per CTA
#define BN       64       // kv rows per tile
#define NKV      (LEN / BN)
#define NTHREADS 256
#define NWARP    8

// raw staging strides (floats)
#define SR_STRIDE 68      // raw K/V: [64 c][68]
#define SQ_STRIDE 132     // raw Q:   [64 c][132]
#define SP_STRIDE 68      // P per warp: [16 t][68] (u32 tf32)

// packed fragment buffers: 64 fragments x 66 words (stride-66 kills bank conflicts)
#define PK_FSTRIDE 66
#define PK_SIZE    (64 * PK_FSTRIDE)    // 4224 words

// smem word layout
#define OFF_PQ   0                       // Q raw (8448) / P packed (8*16*68=8704)
#define OFF_KRAW 8704
#define OFF_VRAW (OFF_KRAW + 64 * SR_STRIDE)   // 13056
#define OFF_KP   (OFF_VRAW + 64 * SR_STRIDE)   // 17408
#define OFF_VP   (OFF_KP + PK_SIZE)            // 21632
#define SMEM_WORDS (OFF_VP + PK_SIZE)          // 25856
#define SMEM_BYTES (SMEM_WORDS * 4)            // 103424

__device__ __forceinline__ uint32_t f2tf32(float f) {
    uint32_t u;
    asm("cvt.rna.tf32.f32 %0, %1;" : "=r"(u) : "f"(f));
    return u;
}

__device__ __forceinline__ float ex2f(float x) {
    float y;
    asm("ex2.approx.ftz.f32 %0, %1;" : "=f"(y) : "f"(x));
    return y;
}

__device__ __forceinline__ void mma_tf32(float c[4], const uint32_t a[4],
                                         uint32_t b0, uint32_t b1) {
    asm volatile(
        "mma.sync.aligned.m16n8k8.row.col.f32.tf32.tf32.f32 "
        "{%0,%1,%2,%3}, {%4,%5,%6,%7}, {%8,%9}, {%0,%1,%2,%3};"
        : "+f"(c[0]), "+f"(c[1]), "+f"(c[2]), "+f"(c[3])
        : "r"(a[0]), "r"(a[1]), "r"(a[2]), "r"(a[3]), "r"(b0), "r"(b1));
}

__device__ __forceinline__ void cp_async16(uint32_t dst, const void* src) {
    asm volatile("cp.async.cg.shared.global [%0], [%1], 16;" :: "r"(dst), "l"(src));
}
__device__ __forceinline__ void cp_commit() {
    asm volatile("cp.async.commit_group;" ::: "memory");
}
__device__ __forceinline__ void cp_wait_all() {
    asm volatile("cp.async.wait_group 0;" ::: "memory");
}

__global__ void __launch_bounds__(NTHREADS, 2)
attn_tf32_kernel(const float* __restrict__ qkv, float* __restrict__ out)
{
    const int qt   = blockIdx.x;          // 0..15 query tile
    const int bh   = blockIdx.y;          // 0..31 batch*head
    const int b    = bh >> 3;
    const int h    = bh & 7;
    const int tid  = threadIdx.x;
    const int warp = tid >> 5;
    const int lane = tid & 31;
    const int g    = lane >> 2;           // 0..7
    const int quad = lane & 3;            // 0..3

    // qkv: [4][1536][2048]; per head: 192 channels (64 q, 64 k, 64 v)
    const float* qbase = qkv + ((size_t)b * 1536 + (size_t)h * 192) * LEN;
    const float* kbase = qbase + (size_t)64 * LEN;
    const float* vbase = qbase + (size_t)128 * LEN;
    const int t0 = qt * BM;

    extern __shared__ float smem[];
    float*    sPQ   = smem;                       // Q raw, later P packed
    float*    sKraw = smem + OFF_KRAW;
    float*    sVraw = smem + OFF_VRAW;
    uint32_t* sKp   = (uint32_t*)(smem + OFF_KP);
    uint32_t* sVp   = (uint32_t*)(smem + OFF_VP);

    const uint32_t sQ_u = (uint32_t)__cvta_generic_to_shared(sPQ);
    const uint32_t sK_u = (uint32_t)__cvta_generic_to_shared(sKraw);
    const uint32_t sV_u = (uint32_t)__cvta_generic_to_shared(sVraw);

    // ---- prologue: async-load Q tile + raw K/V tile 0 ----
    #pragma unroll
    for (int j = 0; j < 8; ++j) {               // Q: 2048 float4
        int i = tid + j * NTHREADS;
        int c = i >> 5, f = i & 31;
        cp_async16(sQ_u + (uint32_t)(c * SQ_STRIDE + f * 4) * 4,
                   qbase + (size_t)c * LEN + t0 + f * 4);
    }
    #pragma unroll
    for (int j = 0; j < 4; ++j) {               // K tile 0
        int i = tid + j * NTHREADS;
        int c = i >> 4, f = i & 15;
        cp_async16(sK_u + (uint32_t)(c * SR_STRIDE + f * 4) * 4,
                   kbase + (size_t)c * LEN + f * 4);
    }
    #pragma unroll
    for (int j = 0; j < 4; ++j) {               // V tile 0
        int i = tid + j * NTHREADS;
        int c = i >> 4, f = i & 15;
        cp_async16(sV_u + (uint32_t)(c * SR_STRIDE + f * 4) * 4,
                   vbase + (size_t)c * LEN + f * 4);
    }
    cp_commit();

    // softmax scale folded into Q, in log2 domain for ex2
    const float qscale = 0.125f * 1.44269504088896340736f;

    // repack-pass constants (thread-fixed)
    const int rp_c  = tid >> 2;                  // c (K) / d (V)
    const int rp_sb = tid & 3;
    // K: addr = ((c>>3)*8 + n)*66 + g*8 + quad*2 + j
    const int k_kbase = (rp_c >> 3) * 8;
    const int k_lo    = (rp_c & 3) * 2 + ((rp_c >> 2) & 1);
    // V: addr = (k*8 + d>>3)*66 + (d&7)*8 + e*2 + (u&1)
    const int v_dbase = (rp_c >> 3) * PK_FSTRIDE + (rp_c & 7) * 8;

    float m0 = -1e30f, m1 = -1e30f, l0 = 0.f, l1 = 0.f;
    float o[8][4];
    #pragma unroll
    for (int n = 0; n < 8; ++n)
        #pragma unroll
        for (int r = 0; r < 4; ++r) o[n][r] = 0.f;

    uint32_t qa[8][4];
    uint32_t* pw = (uint32_t*)sPQ + warp * (16 * SP_STRIDE);

    for (int it = 0; it < NKV; ++it) {
        cp_wait_all();
        __syncthreads();      // raw K/V[it] ready; packed buffers fully consumed

        // ---- convert + repack K raw -> tf32 fragment layout ----
        {
            const float* src = sKraw + rp_c * SR_STRIDE + rp_sb * 16;
            #pragma unroll
            for (int u = 0; u < 4; ++u) {
                float4 v4 = *(const float4*)(src + u * 4);
                int n  = 2 * rp_sb + (u >> 1);
                int gb = (u & 1) * 4;
                uint32_t* d = sKp + (k_kbase + n) * PK_FSTRIDE + k_lo;
                d[(gb + 0) * 8] = f2tf32(v4.x);
                d[(gb + 1) * 8] = f2tf32(v4.y);
                d[(gb + 2) * 8] = f2tf32(v4.z);
                d[(gb + 3) * 8] = f2tf32(v4.w);
            }
        }
        // ---- convert + repack V raw -> tf32 fragment layout ----
        {
            const float* src = sVraw + rp_c * SR_STRIDE + rp_sb * 16;
            #pragma unroll
            for (int u = 0; u < 4; ++u) {
                float4 v4 = *(const float4*)(src + u * 4);
                int k = 2 * rp_sb + (u >> 1);
                uint32_t* d = sVp + k * (8 * PK_FSTRIDE) + v_dbase + (u & 1);
                d[0] = f2tf32(v4.x);
                d[2] = f2tf32(v4.y);
                d[4] = f2tf32(v4.z);
                d[6] = f2tf32(v4.w);
            }
        }
        __syncthreads();      // packed ready; raw free

        if (it == 0) {
            // Q A-fragments (Q raw still intact in sPQ)
            const int tA = warp * 16 + g;
            #pragma unroll
            for (int k = 0; k < 8; ++k) {
                int c0 = k * 8 + quad;
                qa[k][0] = f2tf32(sPQ[c0 * SQ_STRIDE + tA] * qscale);
                qa[k][1] = f2tf32(sPQ[c0 * SQ_STRIDE + tA + 8] * qscale);
                qa[k][2] = f2tf32(sPQ[(c0 + 4) * SQ_STRIDE + tA] * qscale);
                qa[k][3] = f2tf32(sPQ[(c0 + 4) * SQ_STRIDE + tA + 8] * qscale);
            }
            __syncthreads();  // everyone has Q before region becomes P
        }

        // prefetch next raw K/V tile
        if (it + 1 < NKV) {
            const int s1 = (it + 1) * BN;
            #pragma unroll
            for (int j = 0; j < 4; ++j) {
                int i = tid + j * NTHREADS;
                int c = i >> 4, f = i & 15;
                cp_async16(sK_u + (uint32_t)(c * SR_STRIDE + f * 4) * 4,
                           kbase + (size_t)c * LEN + s1 + f * 4);
            }
            #pragma unroll
            for (int j = 0; j < 4; ++j) {
                int i = tid + j * NTHREADS;
                int c = i >> 4, f = i & 15;
                cp_async16(sV_u + (uint32_t)(c * SR_STRIDE + f * 4) * 4,
                           vbase + (size_t)c * LEN + s1 + f * 4);
            }
            cp_commit();
        }

        // ---- S = (Q*scale) @ K : B operands are packed LDS.64 ----
        float sc[8][4];
        #pragma unroll
        for (int n = 0; n < 8; ++n)
            #pragma unroll
            for (int r = 0; r < 4; ++r) sc[n][r] = 0.f;

        #pragma unroll
        for (int k = 0; k < 8; ++k) {
            #pragma unroll
            for (int n = 0; n < 8; ++n) {
                uint2 bb = *(const uint2*)(sKp + (k * 8 + n) * PK_FSTRIDE + lane * 2);
                mma_tf32(sc[n], qa[k], bb.x, bb.y);
            }
        }

        // ---- online softmax (log2 domain) ----
        float tm0 = -1e30f, tm1 = -1e30f;
        #pragma unroll
        for (int n = 0; n < 8; ++n) {
            tm0 = fmaxf(tm0, fmaxf(sc[n][0], sc[n][1]));
            tm1 = fmaxf(tm1, fmaxf(sc[n][2], sc[n][3]));
        }
        tm0 = fmaxf(tm0, __shfl_xor_sync(0xffffffffu, tm0, 1));
        tm0 = fmaxf(tm0, __shfl_xor_sync(0xffffffffu, tm0, 2));
        tm1 = fmaxf(tm1, __shfl_xor_sync(0xffffffffu, tm1, 1));
        tm1 = fmaxf(tm1, __shfl_xor_sync(0xffffffffu, tm1, 2));

        const float mn0 = fmaxf(m0, tm0);
        const float mn1 = fmaxf(m1, tm1);
        const float al0 = ex2f(m0 - mn0);
        const float al1 = ex2f(m1 - mn1);
        m0 = mn0; m1 = mn1;

        float ps0 = 0.f, ps1 = 0.f;
        #pragma unroll
        for (int n = 0; n < 8; ++n) {
            sc[n][0] = ex2f(sc[n][0] - mn0);
            sc[n][1] = ex2f(sc[n][1] - mn0);
            sc[n][2] = ex2f(sc[n][2] - mn1);
            sc[n][3] = ex2f(sc[n][3] - mn1);
            ps0 += sc[n][0] + sc[n][1];
            ps1 += sc[n][2] + sc[n][3];
        }
        l0 = l0 * al0 + ps0;
        l1 = l1 * al1 + ps1;

        #pragma unroll
        for (int n = 0; n < 8; ++n) {
            o[n][0] *= al0; o[n][1] *= al0;
            o[n][2] *= al1; o[n][3] *= al1;
        }

        // ---- P: store already-converted tf32 (C-layout -> row layout) ----
        #pragma unroll
        for (int n = 0; n < 8; ++n) {
            pw[g * SP_STRIDE + n * 8 + quad * 2]           = f2tf32(sc[n][0]);
            pw[g * SP_STRIDE + n * 8 + quad * 2 + 1]       = f2tf32(sc[n][1]);
            pw[(g + 8) * SP_STRIDE + n * 8 + quad * 2]     = f2tf32(sc[n][2]);
            pw[(g + 8) * SP_STRIDE + n * 8 + quad * 2 + 1] = f2tf32(sc[n][3]);
        }
        __syncwarp();

        // ---- O += P @ V^T : pa plain LDS.32, B packed LDS.64 ----
        #pragma unroll
        for (int k = 0; k < 8; ++k) {
            uint32_t pa[4];
            pa[0] = pw[g * SP_STRIDE + k * 8 + quad];
            pa[1] = pw[(g + 8) * SP_STRIDE + k * 8 + quad];
            pa[2] = pw[g * SP_STRIDE + k * 8 + quad + 4];
            pa[3] = pw[(g + 8) * SP_STRIDE + k * 8 + quad + 4];
            #pragma unroll
            for (int n = 0; n < 8; ++n) {
                uint2 bb = *(const uint2*)(sVp + (k * 8 + n) * PK_FSTRIDE + lane * 2);
                mma_tf32(o[n], pa, bb.x, bb.y);
            }
        }
        __syncwarp();
    }

    // ---- finalize: reduce l across the quad, normalize, store ----
    l0 += __shfl_xor_sync(0xffffffffu, l0, 1);
    l0 += __shfl_xor_sync(0xffffffffu, l0, 2);
    l1 += __shfl_xor_sync(0xffffffffu, l1, 1);
    l1 += __shfl_xor_sync(0xffffffffu, l1, 2);
    const float inv0 = 1.f / l0;
    const float inv1 = 1.f / l1;

    // out: [b][h*64 + d][t]
    float* obase = out + ((size_t)b * 512 + (size_t)h * 64) * LEN + t0 + warp * 16;
    #pragma unroll
    for (int n = 0; n < 8; ++n) {
        const int d0 = n * 8 + quad * 2;
        obase[(size_t)d0 * LEN + g]           = o[n][0] * inv0;
        obase[(size_t)(d0 + 1) * LEN + g]     = o[n][1] * inv0;
        obase[(size_t)d0 * LEN + g + 8]       = o[n][2] * inv1;
        obase[(size_t)(d0 + 1) * LEN + g + 8] = o[n][3] * inv1;
    }
}

extern "C" void kernel_launch(void* const* d_in, const int* in_sizes, int n_in,
                              void* d_out, int out_size) {
    const float* qkv = (const float*)d_in[0];
    float* out = (float*)d_out;

    cudaFuncSetAttribute(attn_tf32_kernel,
                         cudaFuncAttributeMaxDynamicSharedMemorySize, SMEM_BYTES);

    dim3 grid(LEN / BM, 32);
    attn_tf32_kernel<<<grid, NTHREADS, SMEM_BYTES>>>(qkv, out);
}

// round 4
// speedup vs baseline: 1.2506x; 1.2506x over previous
#include <cuda_runtime.h>
#include <cstdint>

#define LEN      2048
#define BM       128      // query rows per CTA
#define BN       64       // kv rows per tile
#define NKV      (LEN / BN)
#define NTHREADS 256

// strides in floats/words
#define SR_STRIDE 68       // raw K/V: [64 c][68]
#define SQ_STRIDE 132      // staged Q: [64 c][132]
#define SP_STRIDE 36       // P per warp: [32 rows][36]

#define KV_BUF    (64 * SR_STRIDE)          // 4352 words per K or V buffer
#define P_WARP    (32 * SP_STRIDE)          // 1152 words per warp

// smem word layout
#define OFF_P     0                         // 8 warps * 1152 = 9216 (Q staged here in prologue)
#define OFF_KRAW  9216                      // 2 buffers * 4352
#define OFF_VRAW  (OFF_KRAW + 2 * KV_BUF)   // 17920
#define SMEM_WORDS (OFF_VRAW + 2 * KV_BUF)  // 26624
#define SMEM_BYTES (SMEM_WORDS * 4)         // 106496

// end-of-kernel combine region aliases the raw K/V buffers
#define OFF_CMB_O  OFF_KRAW                 // 4 pairs * 32 rows * 66 = 8448 words
#define OFF_CMB_M  (OFF_CMB_O + 8448)       // 128 words
#define OFF_CMB_L  (OFF_CMB_M + 128)        // 128 words

__device__ __forceinline__ uint32_t f2tf32(float f) {
    uint32_t u;
    asm("cvt.rna.tf32.f32 %0, %1;" : "=r"(u) : "f"(f));
    return u;
}

__device__ __forceinline__ float ex2f(float x) {
    float y;
    asm("ex2.approx.ftz.f32 %0, %1;" : "=f"(y) : "f"(x));
    return y;
}

__device__ __forceinline__ void mma_tf32(float c[4], const uint32_t a[4],
                                         uint32_t b0, uint32_t b1) {
    asm volatile(
        "mma.sync.aligned.m16n8k8.row.col.f32.tf32.tf32.f32 "
        "{%0,%1,%2,%3}, {%4,%5,%6,%7}, {%8,%9}, {%0,%1,%2,%3};"
        : "+f"(c[0]), "+f"(c[1]), "+f"(c[2]), "+f"(c[3])
        : "r"(a[0]), "r"(a[1]), "r"(a[2]), "r"(a[3]), "r"(b0), "r"(b1));
}

__device__ __forceinline__ void cp_async16(uint32_t dst, const void* src) {
    asm volatile("cp.async.cg.shared.global [%0], [%1], 16;" :: "r"(dst), "l"(src));
}
__device__ __forceinline__ void cp_commit() {
    asm volatile("cp.async.commit_group;" ::: "memory");
}
__device__ __forceinline__ void cp_wait_all() {
    asm volatile("cp.async.wait_group 0;" ::: "memory");
}

__global__ void __launch_bounds__(NTHREADS, 1)
attn_tf32_kernel(const float* __restrict__ qkv, float* __restrict__ out)
{
    const int qt   = blockIdx.x;          // query tile 0..15
    const int bh   = blockIdx.y;          // 0..31 batch*head
    const int b    = bh >> 3;
    const int hd   = bh & 7;
    const int tid  = threadIdx.x;
    const int warp = tid >> 5;
    const int wm   = warp >> 1;           // 0..3 : M block (32 rows)
    const int wn   = warp & 1;            // 0..1 : kv half (32 cols)
    const int lane = tid & 31;
    const int g    = lane >> 2;           // 0..7
    const int quad = lane & 3;            // 0..3

    const float* qbase = qkv + ((size_t)b * 1536 + (size_t)hd * 192) * LEN;
    const float* kbase = qbase + (size_t)64 * LEN;
    const float* vbase = qbase + (size_t)128 * LEN;
    const int t0 = qt * BM;

    extern __shared__ float smem[];
    float* sQstage = smem + OFF_P;             // aliases P region (prologue only)
    float* sKraw   = smem + OFF_KRAW;
    float* sVraw   = smem + OFF_VRAW;
    uint32_t* sPw  = (uint32_t*)(smem + OFF_P) + warp * P_WARP;

    const uint32_t sQ_u = (uint32_t)__cvta_generic_to_shared(sQstage);
    const uint32_t sK_u = (uint32_t)__cvta_generic_to_shared(sKraw);
    const uint32_t sV_u = (uint32_t)__cvta_generic_to_shared(sVraw);

    // ---- prologue: async-load Q tile + raw K/V tile 0 (buffer 0) ----
    #pragma unroll
    for (int j = 0; j < 8; ++j) {               // Q: 2048 float4
        int i = tid + j * NTHREADS;
        int c = i >> 5, f = i & 31;
        cp_async16(sQ_u + (uint32_t)(c * SQ_STRIDE + f * 4) * 4,
                   qbase + (size_t)c * LEN + t0 + f * 4);
    }
    #pragma unroll
    for (int j = 0; j < 4; ++j) {               // K tile 0
        int i = tid + j * NTHREADS;
        int c = i >> 4, f = i & 15;
        cp_async16(sK_u + (uint32_t)(c * SR_STRIDE + f * 4) * 4,
                   kbase + (size_t)c * LEN + f * 4);
    }
    #pragma unroll
    for (int j = 0; j < 4; ++j) {               // V tile 0
        int i = tid + j * NTHREADS;
        int c = i >> 4, f = i & 15;
        cp_async16(sV_u + (uint32_t)(c * SR_STRIDE + f * 4) * 4,
                   vbase + (size_t)c * LEN + f * 4);
    }
    cp_commit();

    const float qscale = 0.125f * 1.44269504088896340736f;  // scale * log2(e)

    // per-warp state: rows wm*32 + r*16 + h*8 + g  (r in {0,1}, h in {0,1})
    float m[2][2], l[2][2];
    #pragma unroll
    for (int r = 0; r < 2; ++r)
        #pragma unroll
        for (int h = 0; h < 2; ++h) { m[r][h] = -1e30f; l[r][h] = 0.f; }

    float o[2][8][4];
    #pragma unroll
    for (int r = 0; r < 2; ++r)
        #pragma unroll
        for (int n = 0; n < 8; ++n)
            #pragma unroll
            for (int s = 0; s < 4; ++s) o[r][n][s] = 0.f;

    uint32_t qa[8][2][4];    // [kstep][rowblock][frag]

    for (int it = 0; it < NKV; ++it) {
        cp_wait_all();
        __syncthreads();      // raw K/V[it] ready

        if (it == 0) {
            // Q A-fragments for our 32 rows (scale folded in)
            #pragma unroll
            for (int k = 0; k < 8; ++k) {
                int c0 = k * 8 + quad;
                #pragma unroll
                for (int r = 0; r < 2; ++r) {
                    int tA = wm * 32 + r * 16 + g;
                    qa[k][r][0] = f2tf32(sQstage[c0 * SQ_STRIDE + tA] * qscale);
                    qa[k][r][1] = f2tf32(sQstage[c0 * SQ_STRIDE + tA + 8] * qscale);
                    qa[k][r][2] = f2tf32(sQstage[(c0 + 4) * SQ_STRIDE + tA] * qscale);
                    qa[k][r][3] = f2tf32(sQstage[(c0 + 4) * SQ_STRIDE + tA + 8] * qscale);
                }
            }
            __syncthreads();  // Q consumed before region becomes P
        }

        // prefetch next raw K/V tile into other buffer
        if (it + 1 < NKV) {
            const int s1 = (it + 1) * BN;
            const uint32_t koff = sK_u + (uint32_t)(((it + 1) & 1) * KV_BUF) * 4;
            const uint32_t voff = sV_u + (uint32_t)(((it + 1) & 1) * KV_BUF) * 4;
            #pragma unroll
            for (int j = 0; j < 4; ++j) {
                int i = tid + j * NTHREADS;
                int c = i >> 4, f = i & 15;
                cp_async16(koff + (uint32_t)(c * SR_STRIDE + f * 4) * 4,
                           kbase + (size_t)c * LEN + s1 + f * 4);
            }
            #pragma unroll
            for (int j = 0; j < 4; ++j) {
                int i = tid + j * NTHREADS;
                int c = i >> 4, f = i & 15;
                cp_async16(voff + (uint32_t)(c * SR_STRIDE + f * 4) * 4,
                           vbase + (size_t)c * LEN + s1 + f * 4);
            }
            cp_commit();
        }

        const float* kb = sKraw + (it & 1) * KV_BUF;
        const float* vb = sVraw + (it & 1) * KV_BUF;

        // ---- S = Q @ K over our (32 rows x 32 kv-half) ----
        float sc[2][4][4];
        #pragma unroll
        for (int r = 0; r < 2; ++r)
            #pragma unroll
            for (int n = 0; n < 4; ++n)
                #pragma unroll
                for (int s = 0; s < 4; ++s) sc[r][n][s] = 0.f;

        #pragma unroll
        for (int k = 0; k < 8; ++k) {
            #pragma unroll
            for (int n = 0; n < 4; ++n) {
                int sv = wn * 32 + n * 8 + g;
                uint32_t b0 = f2tf32(kb[(k * 8 + quad) * SR_STRIDE + sv]);
                uint32_t b1 = f2tf32(kb[(k * 8 + quad + 4) * SR_STRIDE + sv]);
                mma_tf32(sc[0][n], qa[k][0], b0, b1);
                mma_tf32(sc[1][n], qa[k][1], b0, b1);
            }
        }

        // ---- online softmax over OWN kv-half (independent per warp) ----
        float tm[2][2] = {{-1e30f, -1e30f}, {-1e30f, -1e30f}};
        #pragma unroll
        for (int r = 0; r < 2; ++r)
            #pragma unroll
            for (int n = 0; n < 4; ++n) {
                tm[r][0] = fmaxf(tm[r][0], fmaxf(sc[r][n][0], sc[r][n][1]));
                tm[r][1] = fmaxf(tm[r][1], fmaxf(sc[r][n][2], sc[r][n][3]));
            }
        #pragma unroll
        for (int r = 0; r < 2; ++r)
            #pragma unroll
            for (int h = 0; h < 2; ++h) {
                tm[r][h] = fmaxf(tm[r][h], __shfl_xor_sync(0xffffffffu, tm[r][h], 1));
                tm[r][h] = fmaxf(tm[r][h], __shfl_xor_sync(0xffffffffu, tm[r][h], 2));
            }

        float al[2][2];
        #pragma unroll
        for (int r = 0; r < 2; ++r)
            #pragma unroll
            for (int h = 0; h < 2; ++h) {
                float mn = fmaxf(m[r][h], tm[r][h]);
                al[r][h] = ex2f(m[r][h] - mn);
                m[r][h] = mn;
            }

        float ps[2][2] = {{0.f, 0.f}, {0.f, 0.f}};
        #pragma unroll
        for (int r = 0; r < 2; ++r)
            #pragma unroll
            for (int n = 0; n < 4; ++n) {
                sc[r][n][0] = ex2f(sc[r][n][0] - m[r][0]);
                sc[r][n][1] = ex2f(sc[r][n][1] - m[r][0]);
                sc[r][n][2] = ex2f(sc[r][n][2] - m[r][1]);
                sc[r][n][3] = ex2f(sc[r][n][3] - m[r][1]);
                ps[r][0] += sc[r][n][0] + sc[r][n][1];
                ps[r][1] += sc[r][n][2] + sc[r][n][3];
            }
        #pragma unroll
        for (int r = 0; r < 2; ++r)
            #pragma unroll
            for (int h = 0; h < 2; ++h)
                l[r][h] = l[r][h] * al[r][h] + ps[r][h];

        #pragma unroll
        for (int r = 0; r < 2; ++r)
            #pragma unroll
            for (int n = 0; n < 8; ++n) {
                o[r][n][0] *= al[r][0]; o[r][n][1] *= al[r][0];
                o[r][n][2] *= al[r][1]; o[r][n][3] *= al[r][1];
            }

        // ---- P (tf32) to per-warp smem: [32 local rows][32 local s] ----
        #pragma unroll
        for (int r = 0; r < 2; ++r)
            #pragma unroll
            for (int n = 0; n < 4; ++n) {
                int row0 = r * 16 + g;
                sPw[row0 * SP_STRIDE + n * 8 + quad * 2]           = f2tf32(sc[r][n][0]);
                sPw[row0 * SP_STRIDE + n * 8 + quad * 2 + 1]       = f2tf32(sc[r][n][1]);
                sPw[(row0 + 8) * SP_STRIDE + n * 8 + quad * 2]     = f2tf32(sc[r][n][2]);
                sPw[(row0 + 8) * SP_STRIDE + n * 8 + quad * 2 + 1] = f2tf32(sc[r][n][3]);
            }
        __syncwarp();

        // ---- O += P @ V^T over own s-half (k = 32), all 64 d ----
        #pragma unroll
        for (int k = 0; k < 4; ++k) {
            uint32_t pa[2][4];
            #pragma unroll
            for (int r = 0; r < 2; ++r) {
                pa[r][0] = sPw[(r * 16 + g) * SP_STRIDE + k * 8 + quad];
                pa[r][1] = sPw[(r * 16 + g + 8) * SP_STRIDE + k * 8 + quad];
                pa[r][2] = sPw[(r * 16 + g) * SP_STRIDE + k * 8 + quad + 4];
                pa[r][3] = sPw[(r * 16 + g + 8) * SP_STRIDE + k * 8 + quad + 4];
            }
            #pragma unroll
            for (int n = 0; n < 8; ++n) {
                int sv = wn * 32 + k * 8 + quad;
                uint32_t b0 = f2tf32(vb[(n * 8 + g) * SR_STRIDE + sv]);
                uint32_t b1 = f2tf32(vb[(n * 8 + g) * SR_STRIDE + sv + 4]);
                mma_tf32(o[0][n], pa[0], b0, b1);
                mma_tf32(o[1][n], pa[1], b0, b1);
            }
        }
        __syncwarp();
    }

    // ---- reduce l across the quad (lane-local partial row sums!) ----
    #pragma unroll
    for (int r = 0; r < 2; ++r)
        #pragma unroll
        for (int h = 0; h < 2; ++h) {
            l[r][h] += __shfl_xor_sync(0xffffffffu, l[r][h], 1);
            l[r][h] += __shfl_xor_sync(0xffffffffu, l[r][h], 2);
        }

    // ---- combine the two kv-half warps (split-KV merge), then store ----
    __syncthreads();   // all tiles done; raw region free for combine

    float* sO = smem + OFF_CMB_O + wm * (32 * 66);
    float* sM = smem + OFF_CMB_M + wm * 32;
    float* sL = smem + OFF_CMB_L + wm * 32;

    if (wn == 1) {
        if (quad == 0) {
            #pragma unroll
            for (int r = 0; r < 2; ++r)
                #pragma unroll
                for (int h = 0; h < 2; ++h) {
                    int row = r * 16 + h * 8 + g;
                    sM[row] = m[r][h];
                    sL[row] = l[r][h];
                }
        }
        #pragma unroll
        for (int r = 0; r < 2; ++r)
            #pragma unroll
            for (int n = 0; n < 8; ++n) {
                int row0 = r * 16 + g;
                sO[row0 * 66 + n * 8 + quad * 2]           = o[r][n][0];
                sO[row0 * 66 + n * 8 + quad * 2 + 1]       = o[r][n][1];
                sO[(row0 + 8) * 66 + n * 8 + quad * 2]     = o[r][n][2];
                sO[(row0 + 8) * 66 + n * 8 + quad * 2 + 1] = o[r][n][3];
            }
    }
    __syncthreads();

    if (wn == 0) {
        float a[2][2], ao[2][2], inv[2][2];
        #pragma unroll
        for (int r = 0; r < 2; ++r)
            #pragma unroll
            for (int h = 0; h < 2; ++h) {
                int row = r * 16 + h * 8 + g;
                float mo = sM[row];
                float lo = sL[row];
                float M  = fmaxf(m[r][h], mo);
                a[r][h]  = ex2f(m[r][h] - M);
                ao[r][h] = ex2f(mo - M);
                inv[r][h] = 1.f / (l[r][h] * a[r][h] + lo * ao[r][h]);
            }

        float* obase = out + ((size_t)b * 512 + (size_t)hd * 64) * LEN + t0 + wm * 32;
        #pragma unroll
        for (int r = 0; r < 2; ++r)
            #pragma unroll
            for (int n = 0; n < 8; ++n) {
                int row0 = r * 16 + g;
                int d0 = n * 8 + quad * 2;
                float v0 = o[r][n][0] * a[r][0] + sO[row0 * 66 + d0] * ao[r][0];
                float v1 = o[r][n][1] * a[r][0] + sO[row0 * 66 + d0 + 1] * ao[r][0];
                float v2 = o[r][n][2] * a[r][1] + sO[(row0 + 8) * 66 + d0] * ao[r][1];
                float v3 = o[r][n][3] * a[r][1] + sO[(row0 + 8) * 66 + d0 + 1] * ao[r][1];
                obase[(size_t)d0 * LEN + row0]           = v0 * inv[r][0];
                obase[(size_t)(d0 + 1) * LEN + row0]     = v1 * inv[r][0];
                obase[(size_t)d0 * LEN + row0 + 8]       = v2 * inv[r][1];
                obase[(size_t)(d0 + 1) * LEN + row0 + 8] = v3 * inv[r][1];
            }
    }
}

extern "C" void kernel_launch(void* const* d_in, const int* in_sizes, int n_in,
                              void* d_out, int out_size) {
    const float* qkv = (const float*)d_in[0];
    float* out = (float*)d_out;

    cudaFuncSetAttribute(attn_tf32_kernel,
                         cudaFuncAttributeMaxDynamicSharedMemorySize, SMEM_BYTES);

    dim3 grid(LEN / BM, 32);
    attn_tf32_kernel<<<grid, NTHREADS, SMEM_BYTES>>>(qkv, out);
}